// round 1
// baseline (speedup 1.0000x reference)
#include <cuda_runtime.h>
#include <math.h>

#define NE 16
#define DIM 512
#define HID 1024
#define MAXT 8192
#define MAXSLOTS (MAXT * 2)

// ---------------- scratch (device globals; no allocation allowed) ----------
__device__ int   g_cnt[NE];
__device__ int   g_cursor[NE];
__device__ int   g_off[NE + 1];
__device__ int   g_tp[NE + 1];          // m-tile prefix (BM=128)
__device__ int   g_tidx[MAXSLOTS];      // per (token,k): expert id
__device__ float g_tw[MAXSLOTS];        // per (token,k): combine weight
__device__ int   g_slot_token[MAXSLOTS];
__device__ int   g_slot_of[MAXSLOTS];   // (token,k) -> slot
__device__ float g_h[(size_t)MAXSLOTS * HID];  // 64 MB
__device__ float g_o[(size_t)MAXSLOTS * DIM];  // 32 MB

// ---------------- init ------------------------------------------------------
__global__ void k_init() {
    if (threadIdx.x < NE) g_cnt[threadIdx.x] = 0;
}

// ---------------- router: logits, softmax top-2, counts --------------------
__global__ void k_router(const float* __restrict__ x,
                         const float* __restrict__ Wr,
                         const float* __restrict__ br, int T) {
    int w    = (blockIdx.x * blockDim.x + threadIdx.x) >> 5;
    int lane = threadIdx.x & 31;
    if (w >= T) return;

    float acc[NE];
#pragma unroll
    for (int e = 0; e < NE; e++) acc[e] = 0.f;

    const float* xr = x + (size_t)w * DIM;
    for (int d = lane; d < DIM; d += 32) {
        float xv = xr[d];
        const float* wr = Wr + d * NE;
#pragma unroll
        for (int e = 0; e < NE; e++) acc[e] = fmaf(xv, wr[e], acc[e]);
    }
#pragma unroll
    for (int off = 16; off; off >>= 1) {
#pragma unroll
        for (int e = 0; e < NE; e++)
            acc[e] += __shfl_xor_sync(0xffffffffu, acc[e], off);
    }
    if (lane == 0) {
#pragma unroll
        for (int e = 0; e < NE; e++) acc[e] += br[e];
        // top-1 (strict > => lowest index on ties, matching lax.top_k)
        int b0 = 0; float l0 = acc[0];
#pragma unroll
        for (int e = 1; e < NE; e++) if (acc[e] > l0) { l0 = acc[e]; b0 = e; }
        int b1 = -1; float l1 = -3.0e38f;
#pragma unroll
        for (int e = 0; e < NE; e++)
            if (e != b0 && acc[e] > l1) { l1 = acc[e]; b1 = e; }
        // renormalized top-2 softmax weights == pairwise sigmoid
        float w0 = 1.f / (1.f + expf(l1 - l0));
        float w1 = 1.f - w0;
        g_tidx[2 * w]     = b0;  g_tidx[2 * w + 1] = b1;
        g_tw[2 * w]       = w0;  g_tw[2 * w + 1]   = w1;
        atomicAdd(&g_cnt[b0], 1);
        atomicAdd(&g_cnt[b1], 1);
    }
}

// ---------------- scan: offsets, cursors, tile prefix -----------------------
__global__ void k_scan() {
    if (threadIdx.x == 0) {
        g_off[0] = 0; g_tp[0] = 0;
        for (int e = 0; e < NE; e++) {
            int c = g_cnt[e];
            g_off[e + 1] = g_off[e] + c;
            g_cursor[e]  = g_off[e];
            g_tp[e + 1]  = g_tp[e] + (c + 127) / 128;
        }
    }
}

// ---------------- scatter: slot permutation ---------------------------------
__global__ void k_scatter(int T) {
    int i = blockIdx.x * blockDim.x + threadIdx.x;
    if (i >= 2 * T) return;
    int e = g_tidx[i];
    int pos = atomicAdd(&g_cursor[e], 1);
    g_slot_token[pos] = i >> 1;
    g_slot_of[i]      = pos;
}

// ---------------- grouped GEMM (fp32, tiled 128x64x16) ----------------------
// FIRST: C=g_h = gelu(gather(x) @ W1[e] + b1[e]),  N=HID, K=DIM
// !FIRST: C=g_o = g_h @ W2[e] + b2[e],             N=DIM, K=HID
template <bool FIRST>
__global__ void __launch_bounds__(256)
k_gemm(const float* __restrict__ X, const float* __restrict__ Bw,
       const float* __restrict__ bias) {
    constexpr int N  = FIRST ? HID : DIM;
    constexpr int K  = FIRST ? DIM : HID;
    constexpr int BM = 128, BN = 64, BK = 16;
    constexpr int NT = N / BN;

    __shared__ float As[BK][BM + 4];
    __shared__ float Bs[BK][BN];

    const int tid = threadIdx.x;
    const int tx  = tid & 15;        // 0..15 : 4 output cols each
    const int ty  = tid >> 4;        // 0..15 : 8 output rows each
    const int lr0 = tid >> 2;        // A-load row 0..63 (and +64)
    const int lc0 = (tid & 3) * 4;   // A-load k group
    const int lbk = tid >> 4;        // B-load k row
    const int lbn = (tid & 15) * 4;  // B-load n group

    const int total = g_tp[NE] * NT;

    for (int work = blockIdx.x; work < total; work += gridDim.x) {
        const int mt = work / NT;
        const int nt = work - mt * NT;
        int e = 0;
        while (g_tp[e + 1] <= mt) e++;
        const int m0   = g_off[e] + (mt - g_tp[e]) * BM;
        const int mEnd = g_off[e + 1];
        const int n0   = nt * BN;

        const float* Be = Bw + (size_t)e * K * N;

        const int r0 = min(m0 + lr0,      mEnd - 1);
        const int r1 = min(m0 + lr0 + 64, mEnd - 1);
        const float* a0p;
        const float* a1p;
        if (FIRST) {
            a0p = X + (size_t)g_slot_token[r0] * K;
            a1p = X + (size_t)g_slot_token[r1] * K;
        } else {
            a0p = g_h + (size_t)r0 * K;
            a1p = g_h + (size_t)r1 * K;
        }

        float acc[8][4];
#pragma unroll
        for (int i = 0; i < 8; i++)
#pragma unroll
            for (int j = 0; j < 4; j++) acc[i][j] = 0.f;

        for (int k0 = 0; k0 < K; k0 += BK) {
            float4 av0 = *(const float4*)(a0p + k0 + lc0);
            float4 av1 = *(const float4*)(a1p + k0 + lc0);
            float4 bv  = *(const float4*)(Be + (size_t)(k0 + lbk) * N + n0 + lbn);
            __syncthreads();
            As[lc0    ][lr0]      = av0.x;
            As[lc0 + 1][lr0]      = av0.y;
            As[lc0 + 2][lr0]      = av0.z;
            As[lc0 + 3][lr0]      = av0.w;
            As[lc0    ][lr0 + 64] = av1.x;
            As[lc0 + 1][lr0 + 64] = av1.y;
            As[lc0 + 2][lr0 + 64] = av1.z;
            As[lc0 + 3][lr0 + 64] = av1.w;
            *(float4*)&Bs[lbk][lbn] = bv;
            __syncthreads();
#pragma unroll
            for (int k = 0; k < BK; k++) {
                float4 a0 = *(const float4*)&As[k][ty * 8];
                float4 a1 = *(const float4*)&As[k][ty * 8 + 4];
                float4 b  = *(const float4*)&Bs[k][tx * 4];
                float af[8] = {a0.x, a0.y, a0.z, a0.w, a1.x, a1.y, a1.z, a1.w};
                float bf[4] = {b.x, b.y, b.z, b.w};
#pragma unroll
                for (int i = 0; i < 8; i++)
#pragma unroll
                    for (int j = 0; j < 4; j++)
                        acc[i][j] = fmaf(af[i], bf[j], acc[i][j]);
            }
        }

        const int n = n0 + tx * 4;
        float4 bb = *(const float4*)(bias + e * N + n);
#pragma unroll
        for (int i = 0; i < 8; i++) {
            const int m = m0 + ty * 8 + i;
            if (m < mEnd) {
                float4 o;
                o.x = acc[i][0] + bb.x;
                o.y = acc[i][1] + bb.y;
                o.z = acc[i][2] + bb.z;
                o.w = acc[i][3] + bb.w;
                if (FIRST) {
                    o.x = 0.5f * o.x * (1.f + erff(o.x * 0.70710678118654752f));
                    o.y = 0.5f * o.y * (1.f + erff(o.y * 0.70710678118654752f));
                    o.z = 0.5f * o.z * (1.f + erff(o.z * 0.70710678118654752f));
                    o.w = 0.5f * o.w * (1.f + erff(o.w * 0.70710678118654752f));
                    *(float4*)(g_h + (size_t)m * N + n) = o;
                } else {
                    *(float4*)(g_o + (size_t)m * N + n) = o;
                }
            }
        }
    }
}

// ---------------- combine: y = x + w0*o[s0] + w1*o[s1] ----------------------
__global__ void k_combine(const float* __restrict__ x, float* __restrict__ y,
                          int T) {
    int i = blockIdx.x * blockDim.x + threadIdx.x;
    int total = T * (DIM / 4);
    if (i >= total) return;
    int t  = i / (DIM / 4);
    int d  = (i - t * (DIM / 4)) * 4;
    float w0 = g_tw[2 * t], w1 = g_tw[2 * t + 1];
    int   s0 = g_slot_of[2 * t], s1 = g_slot_of[2 * t + 1];
    float4 xv = *(const float4*)(x + (size_t)t * DIM + d);
    float4 o0 = *(const float4*)(g_o + (size_t)s0 * DIM + d);
    float4 o1 = *(const float4*)(g_o + (size_t)s1 * DIM + d);
    float4 r;
    r.x = xv.x + w0 * o0.x + w1 * o1.x;
    r.y = xv.y + w0 * o0.y + w1 * o1.y;
    r.z = xv.z + w0 * o0.z + w1 * o1.z;
    r.w = xv.w + w0 * o0.w + w1 * o1.w;
    *(float4*)(y + (size_t)t * DIM + d) = r;
}

// ---------------- launch -----------------------------------------------------
extern "C" void kernel_launch(void* const* d_in, const int* in_sizes, int n_in,
                              void* d_out, int out_size) {
    const float* x  = (const float*)d_in[0];
    const float* Wr = (const float*)d_in[1];
    const float* br = (const float*)d_in[2];
    const float* W1 = (const float*)d_in[3];
    const float* b1 = (const float*)d_in[4];
    const float* W2 = (const float*)d_in[5];
    const float* b2 = (const float*)d_in[6];
    float* y = (float*)d_out;
    const int T = in_sizes[0] / DIM;

    k_init<<<1, 32>>>();
    k_router<<<(T + 7) / 8, 256>>>(x, Wr, br, T);
    k_scan<<<1, 32>>>();
    k_scatter<<<(2 * T + 255) / 256, 256>>>(T);
    k_gemm<true><<<2048, 256>>>(x, W1, b1);
    k_gemm<false><<<2048, 256>>>(nullptr, W2, b2);
    k_combine<<<(T * (DIM / 4) + 255) / 256, 256>>>(x, y, T);
}

// round 2
// speedup vs baseline: 1.8387x; 1.8387x over previous
#include <cuda_runtime.h>
#include <math.h>

#define NE 16
#define DIM 512
#define HID 1024
#define MAXT 8192
#define MAXSLOTS (MAXT * 2)

// ---------------- scratch (device globals; no allocation allowed) ----------
__device__ int   g_cnt[NE];
__device__ int   g_cursor[NE];
__device__ int   g_off[NE + 1];
__device__ int   g_tp[NE + 1];          // m-tile prefix (BM=128)
__device__ int   g_tidx[MAXSLOTS];      // per (token,k): expert id
__device__ float g_tw[MAXSLOTS];        // per (token,k): combine weight
__device__ int   g_slot_token[MAXSLOTS];
__device__ int   g_slot_of[MAXSLOTS];   // (token,k) -> slot
__device__ float g_h[(size_t)MAXSLOTS * HID];  // 64 MB
__device__ float g_o[(size_t)MAXSLOTS * DIM];  // 32 MB

__device__ __forceinline__ unsigned f2tf32(float f) {
    unsigned u;
    asm("cvt.rna.tf32.f32 %0, %1;" : "=r"(u) : "f"(f));
    return u;
}

// ---------------- init ------------------------------------------------------
__global__ void k_init() {
    if (threadIdx.x < NE) g_cnt[threadIdx.x] = 0;
}

// ---------------- router: logits, softmax top-2, counts --------------------
__global__ void k_router(const float* __restrict__ x,
                         const float* __restrict__ Wr,
                         const float* __restrict__ br, int T) {
    int w    = (blockIdx.x * blockDim.x + threadIdx.x) >> 5;
    int lane = threadIdx.x & 31;
    if (w >= T) return;

    float acc[NE];
#pragma unroll
    for (int e = 0; e < NE; e++) acc[e] = 0.f;

    const float* xr = x + (size_t)w * DIM;
    for (int d = lane; d < DIM; d += 32) {
        float xv = xr[d];
        const float* wr = Wr + d * NE;
#pragma unroll
        for (int e = 0; e < NE; e++) acc[e] = fmaf(xv, wr[e], acc[e]);
    }
#pragma unroll
    for (int off = 16; off; off >>= 1) {
#pragma unroll
        for (int e = 0; e < NE; e++)
            acc[e] += __shfl_xor_sync(0xffffffffu, acc[e], off);
    }
    if (lane == 0) {
#pragma unroll
        for (int e = 0; e < NE; e++) acc[e] += br[e];
        int b0 = 0; float l0 = acc[0];
#pragma unroll
        for (int e = 1; e < NE; e++) if (acc[e] > l0) { l0 = acc[e]; b0 = e; }
        int b1 = -1; float l1 = -3.0e38f;
#pragma unroll
        for (int e = 0; e < NE; e++)
            if (e != b0 && acc[e] > l1) { l1 = acc[e]; b1 = e; }
        float w0 = 1.f / (1.f + expf(l1 - l0));
        float w1 = 1.f - w0;
        g_tidx[2 * w]     = b0;  g_tidx[2 * w + 1] = b1;
        g_tw[2 * w]       = w0;  g_tw[2 * w + 1]   = w1;
        atomicAdd(&g_cnt[b0], 1);
        atomicAdd(&g_cnt[b1], 1);
    }
}

// ---------------- scan: offsets, cursors, tile prefix -----------------------
__global__ void k_scan() {
    if (threadIdx.x == 0) {
        g_off[0] = 0; g_tp[0] = 0;
        for (int e = 0; e < NE; e++) {
            int c = g_cnt[e];
            g_off[e + 1] = g_off[e] + c;
            g_cursor[e]  = g_off[e];
            g_tp[e + 1]  = g_tp[e] + (c + 127) / 128;
        }
    }
}

// ---------------- scatter: slot permutation ---------------------------------
__global__ void k_scatter(int T) {
    int i = blockIdx.x * blockDim.x + threadIdx.x;
    if (i >= 2 * T) return;
    int e = g_tidx[i];
    int pos = atomicAdd(&g_cursor[e], 1);
    g_slot_token[pos] = i >> 1;
    g_slot_of[i]      = pos;
}

// ---------------- grouped GEMM via mma.sync tf32 (128x128x16 tile) ----------
// FIRST: g_h = gelu(gather(x) @ W1[e] + b1[e]),  N=HID, K=DIM
// else:  g_o = g_h @ W2[e] + b2[e],              N=DIM, K=HID
template <bool FIRST>
__global__ void __launch_bounds__(256, 2)
k_gemm(const float* __restrict__ X, const float* __restrict__ Bw,
       const float* __restrict__ bias) {
    constexpr int N  = FIRST ? HID : DIM;
    constexpr int K  = FIRST ? DIM : HID;
    constexpr int BM = 128, BN = 128, BK = 16;
    constexpr int NT = N / BN;

    // stride 136 words => 136 mod 32 == 8: conflict-free fragment LDS
    __shared__ float As[BK][BM + 8];
    __shared__ float Bs[BK][BN + 8];

    const int tid  = threadIdx.x;
    const int wid  = tid >> 5;
    const int lane = tid & 31;
    const int wm   = (wid & 3) * 32;   // warp m-offset (4 warps over M)
    const int wn   = (wid >> 2) * 64;  // warp n-offset (2 warps over N)
    const int g    = lane >> 2;        // groupID 0..7
    const int t    = lane & 3;         // threadID_in_group 0..3

    // A global load: thread -> (row am, 8 consecutive k at offset ak)
    const int am = tid >> 1;
    const int ak = (tid & 1) * 8;
    // B global load: thread -> (k row bk, 8 consecutive n at offset bn)
    const int bk = tid >> 4;
    const int bn = (tid & 15) * 8;

    const int total = g_tp[NE] * NT;

    for (int work = blockIdx.x; work < total; work += gridDim.x) {
        const int mt = work / NT;
        const int nt = work - mt * NT;
        int e = 0;
        while (g_tp[e + 1] <= mt) e++;
        const int m0   = g_off[e] + (mt - g_tp[e]) * BM;
        const int mEnd = g_off[e + 1];
        const int n0   = nt * BN;

        const float* Be = Bw + (size_t)e * K * N + n0;

        const int rA = min(m0 + am, mEnd - 1);
        const float* Ap = FIRST ? X + (size_t)g_slot_token[rA] * K
                                : g_h + (size_t)rA * K;
        const float* Bp = Be + (size_t)bk * N + bn;

        // prefetch first tile
        float4 a0 = *(const float4*)(Ap + ak);
        float4 a1 = *(const float4*)(Ap + ak + 4);
        float4 bb0 = *(const float4*)(Bp);
        float4 bb1 = *(const float4*)(Bp + 4);

        float acc[2][8][4];
#pragma unroll
        for (int mi = 0; mi < 2; mi++)
#pragma unroll
            for (int ni = 0; ni < 8; ni++)
#pragma unroll
                for (int j = 0; j < 4; j++) acc[mi][ni][j] = 0.f;

        for (int k0 = 0; k0 < K; k0 += BK) {
            __syncthreads();
            // store A transposed (k-major rows), converted to tf32
            As[ak + 0][am] = __uint_as_float(f2tf32(a0.x));
            As[ak + 1][am] = __uint_as_float(f2tf32(a0.y));
            As[ak + 2][am] = __uint_as_float(f2tf32(a0.z));
            As[ak + 3][am] = __uint_as_float(f2tf32(a0.w));
            As[ak + 4][am] = __uint_as_float(f2tf32(a1.x));
            As[ak + 5][am] = __uint_as_float(f2tf32(a1.y));
            As[ak + 6][am] = __uint_as_float(f2tf32(a1.z));
            As[ak + 7][am] = __uint_as_float(f2tf32(a1.w));
            float4 bc0, bc1;
            bc0.x = __uint_as_float(f2tf32(bb0.x));
            bc0.y = __uint_as_float(f2tf32(bb0.y));
            bc0.z = __uint_as_float(f2tf32(bb0.z));
            bc0.w = __uint_as_float(f2tf32(bb0.w));
            bc1.x = __uint_as_float(f2tf32(bb1.x));
            bc1.y = __uint_as_float(f2tf32(bb1.y));
            bc1.z = __uint_as_float(f2tf32(bb1.z));
            bc1.w = __uint_as_float(f2tf32(bb1.w));
            *(float4*)&Bs[bk][bn]     = bc0;
            *(float4*)&Bs[bk][bn + 4] = bc1;
            __syncthreads();

            // prefetch next tile while computing this one
            if (k0 + BK < K) {
                a0  = *(const float4*)(Ap + k0 + BK + ak);
                a1  = *(const float4*)(Ap + k0 + BK + ak + 4);
                bb0 = *(const float4*)(Bp + (size_t)(k0 + BK) * N);
                bb1 = *(const float4*)(Bp + (size_t)(k0 + BK) * N + 4);
            }

#pragma unroll
            for (int kk = 0; kk < BK; kk += 8) {
                unsigned af[2][4], bf[8][2];
#pragma unroll
                for (int mi = 0; mi < 2; mi++) {
                    int r = wm + mi * 16 + g;
                    af[mi][0] = __float_as_uint(As[kk + t][r]);
                    af[mi][1] = __float_as_uint(As[kk + t][r + 8]);
                    af[mi][2] = __float_as_uint(As[kk + t + 4][r]);
                    af[mi][3] = __float_as_uint(As[kk + t + 4][r + 8]);
                }
#pragma unroll
                for (int ni = 0; ni < 8; ni++) {
                    int c = wn + ni * 8 + g;
                    bf[ni][0] = __float_as_uint(Bs[kk + t][c]);
                    bf[ni][1] = __float_as_uint(Bs[kk + t + 4][c]);
                }
#pragma unroll
                for (int mi = 0; mi < 2; mi++)
#pragma unroll
                    for (int ni = 0; ni < 8; ni++) {
                        float* c = acc[mi][ni];
                        asm volatile(
                            "mma.sync.aligned.m16n8k8.row.col.f32.tf32.tf32.f32 "
                            "{%0,%1,%2,%3}, {%4,%5,%6,%7}, {%8,%9}, {%0,%1,%2,%3};"
                            : "+f"(c[0]), "+f"(c[1]), "+f"(c[2]), "+f"(c[3])
                            : "r"(af[mi][0]), "r"(af[mi][1]),
                              "r"(af[mi][2]), "r"(af[mi][3]),
                              "r"(bf[ni][0]), "r"(bf[ni][1]));
                    }
            }
        }

        // ---------------- epilogue ----------------
        float* Out = FIRST ? g_h : g_o;
#pragma unroll
        for (int mi = 0; mi < 2; mi++) {
            const int row0 = m0 + wm + mi * 16 + g;
            const int row1 = row0 + 8;
#pragma unroll
            for (int ni = 0; ni < 8; ni++) {
                const int col = n0 + wn + ni * 8 + 2 * t;
                const float2 bb = *(const float2*)(bias + e * N + col);
                float v0 = acc[mi][ni][0] + bb.x;
                float v1 = acc[mi][ni][1] + bb.y;
                float v2 = acc[mi][ni][2] + bb.x;
                float v3 = acc[mi][ni][3] + bb.y;
                if (FIRST) {
                    v0 = 0.5f * v0 * (1.f + erff(v0 * 0.70710678118654752f));
                    v1 = 0.5f * v1 * (1.f + erff(v1 * 0.70710678118654752f));
                    v2 = 0.5f * v2 * (1.f + erff(v2 * 0.70710678118654752f));
                    v3 = 0.5f * v3 * (1.f + erff(v3 * 0.70710678118654752f));
                }
                if (row0 < mEnd) {
                    float2 o = {v0, v1};
                    *(float2*)(Out + (size_t)row0 * N + col) = o;
                }
                if (row1 < mEnd) {
                    float2 o = {v2, v3};
                    *(float2*)(Out + (size_t)row1 * N + col) = o;
                }
            }
        }
    }
}

// ---------------- combine: y = x + w0*o[s0] + w1*o[s1] ----------------------
__global__ void k_combine(const float* __restrict__ x, float* __restrict__ y,
                          int T) {
    int i = blockIdx.x * blockDim.x + threadIdx.x;
    int total = T * (DIM / 4);
    if (i >= total) return;
    int t  = i / (DIM / 4);
    int d  = (i - t * (DIM / 4)) * 4;
    float w0 = g_tw[2 * t], w1 = g_tw[2 * t + 1];
    int   s0 = g_slot_of[2 * t], s1 = g_slot_of[2 * t + 1];
    float4 xv = *(const float4*)(x + (size_t)t * DIM + d);
    float4 o0 = *(const float4*)(g_o + (size_t)s0 * DIM + d);
    float4 o1 = *(const float4*)(g_o + (size_t)s1 * DIM + d);
    float4 r;
    r.x = xv.x + w0 * o0.x + w1 * o1.x;
    r.y = xv.y + w0 * o0.y + w1 * o1.y;
    r.z = xv.z + w0 * o0.z + w1 * o1.z;
    r.w = xv.w + w0 * o0.w + w1 * o1.w;
    *(float4*)(y + (size_t)t * DIM + d) = r;
}

// ---------------- launch -----------------------------------------------------
extern "C" void kernel_launch(void* const* d_in, const int* in_sizes, int n_in,
                              void* d_out, int out_size) {
    const float* x  = (const float*)d_in[0];
    const float* Wr = (const float*)d_in[1];
    const float* br = (const float*)d_in[2];
    const float* W1 = (const float*)d_in[3];
    const float* b1 = (const float*)d_in[4];
    const float* W2 = (const float*)d_in[5];
    const float* b2 = (const float*)d_in[6];
    float* y = (float*)d_out;
    const int T = in_sizes[0] / DIM;

    k_init<<<1, 32>>>();
    k_router<<<(T + 7) / 8, 256>>>(x, Wr, br, T);
    k_scan<<<1, 32>>>();
    k_scatter<<<(2 * T + 255) / 256, 256>>>(T);
    k_gemm<true><<<1184, 256>>>(x, W1, b1);
    k_gemm<false><<<1184, 256>>>(nullptr, W2, b2);
    k_combine<<<(T * (DIM / 4) + 255) / 256, 256>>>(x, y, T);
}

// round 6
// speedup vs baseline: 2.4092x; 1.3103x over previous
#include <cuda_runtime.h>
#include <math.h>
#include <stdint.h>

#define NE 16
#define DIM 512
#define HID 1024
#define MAXT 8192
#define MAXSLOTS (MAXT * 2)

// ---------------- scratch (device globals; no allocation allowed) ----------
__device__ int   g_cnt[NE];
__device__ int   g_cursor[NE];
__device__ int   g_off[NE + 1];
__device__ int   g_tp[NE + 1];
__device__ int   g_tidx[MAXSLOTS];
__device__ float g_tw[MAXSLOTS];
__device__ int   g_slot_token[MAXSLOTS];
__device__ int   g_slot_of[MAXSLOTS];
__device__ float g_h[(size_t)MAXSLOTS * HID];  // gelu(h) fp32, 64 MB
__device__ float g_o[(size_t)MAXSLOTS * DIM];  // expert outputs fp32, 32 MB

// ---------------- PTX helpers ------------------------------------------------
__device__ __forceinline__ uint32_t smem_u32(const void* p) {
    uint32_t a;
    asm("{ .reg .u64 t; cvta.to.shared.u64 t, %1; cvt.u32.u64 %0, t; }"
        : "=r"(a) : "l"(p));
    return a;
}

#define CP_ASYNC16(dst, src) \
    asm volatile("cp.async.cg.shared.global [%0], [%1], 16;" \
                 :: "r"(dst), "l"(src) : "memory")
#define CP_COMMIT() asm volatile("cp.async.commit_group;" ::: "memory")
#define CP_WAIT1()  asm volatile("cp.async.wait_group 1;"  ::: "memory")

// tf32 mma, operands are raw fp32 bit patterns (HW truncates to tf32)
#define MMA_TF32(c, a0, a1, a2, a3, b0, b1) \
    asm volatile("mma.sync.aligned.m16n8k8.row.col.f32.tf32.tf32.f32 " \
                 "{%0,%1,%2,%3}, {%4,%5,%6,%7}, {%8,%9}, {%0,%1,%2,%3};" \
                 : "+f"((c)[0]), "+f"((c)[1]), "+f"((c)[2]), "+f"((c)[3]) \
                 : "r"(a0), "r"(a1), "r"(a2), "r"(a3), "r"(b0), "r"(b1))

// ---------------- small kernels (verified in rounds 1-2) --------------------
__global__ void k_init() { if (threadIdx.x < NE) g_cnt[threadIdx.x] = 0; }

__global__ void k_router(const float* __restrict__ x,
                         const float* __restrict__ Wr,
                         const float* __restrict__ br, int T) {
    int w = (blockIdx.x * blockDim.x + threadIdx.x) >> 5;
    int lane = threadIdx.x & 31;
    if (w >= T) return;
    float acc[NE];
#pragma unroll
    for (int e = 0; e < NE; e++) acc[e] = 0.f;
    const float* xr = x + (size_t)w * DIM;
    for (int d = lane; d < DIM; d += 32) {
        float xv = xr[d];
        const float* wr = Wr + d * NE;
#pragma unroll
        for (int e = 0; e < NE; e++) acc[e] = fmaf(xv, wr[e], acc[e]);
    }
#pragma unroll
    for (int off = 16; off; off >>= 1)
#pragma unroll
        for (int e = 0; e < NE; e++)
            acc[e] += __shfl_xor_sync(0xffffffffu, acc[e], off);
    if (lane == 0) {
#pragma unroll
        for (int e = 0; e < NE; e++) acc[e] += br[e];
        int b0 = 0; float l0 = acc[0];
#pragma unroll
        for (int e = 1; e < NE; e++) if (acc[e] > l0) { l0 = acc[e]; b0 = e; }
        int b1 = -1; float l1 = -3.0e38f;
#pragma unroll
        for (int e = 0; e < NE; e++)
            if (e != b0 && acc[e] > l1) { l1 = acc[e]; b1 = e; }
        float w0 = 1.f / (1.f + expf(l1 - l0));
        g_tidx[2 * w] = b0; g_tidx[2 * w + 1] = b1;
        g_tw[2 * w] = w0;   g_tw[2 * w + 1] = 1.f - w0;
        atomicAdd(&g_cnt[b0], 1);
        atomicAdd(&g_cnt[b1], 1);
    }
}

__global__ void k_scan() {
    if (threadIdx.x == 0) {
        g_off[0] = 0; g_tp[0] = 0;
        for (int e = 0; e < NE; e++) {
            int c = g_cnt[e];
            g_off[e + 1] = g_off[e] + c;
            g_cursor[e] = g_off[e];
            g_tp[e + 1] = g_tp[e] + (c + 127) / 128;
        }
    }
}

__global__ void k_scatter(int T) {
    int i = blockIdx.x * blockDim.x + threadIdx.x;
    if (i >= 2 * T) return;
    int e = g_tidx[i];
    int pos = atomicAdd(&g_cursor[e], 1);
    g_slot_token[pos] = i >> 1;
    g_slot_of[i] = pos;
}

__device__ __forceinline__ float gelu(float v) {
    return 0.5f * v * (1.f + erff(v * 0.70710678118654752f));
}

// ---------------- grouped GEMM: tf32 mma.sync + cp.async double buffer ------
// FIRST: g_h = gelu(gather(x) @ W1[e] + b1[e]),  N=HID, K=DIM
// else : g_o = g_h @ W2[e] + b2[e],              N=DIM, K=HID
// Tile BM=128 x BN=128 x BK=32, fp32 operands in smem (truncated tf32 in mma).
// A smem: [128 rows][32 k + 4 pad] -> stride 36 words (fragment bank = 4*lr+lt)
// B smem: [32 k][128 n + 8 pad]   -> stride 136 words (fragment bank = 8*lt+lr)
#define A_WORDS (128 * 36)            // 4608
#define B_WORDS (32 * 136)            // 4352
#define STAGE_WORDS (A_WORDS + B_WORDS)
#define STAGE_BYTES (STAGE_WORDS * 4) // 35840
#define GEMM_SMEM   (2 * STAGE_BYTES) // 71680

template <bool FIRST>
__global__ void __launch_bounds__(256)
k_gemm(const float* __restrict__ X, const float* __restrict__ Bw,
       const float* __restrict__ bias) {
    constexpr int N  = FIRST ? HID : DIM;
    constexpr int K  = FIRST ? DIM : HID;
    constexpr int KT = K / 32;
    constexpr int NT = N / 128;

    extern __shared__ uint32_t dsw[];
    const uint32_t sb = smem_u32(dsw);

    const int tid  = threadIdx.x;
    const int lane = tid & 31;
    const int wid  = tid >> 5;
    const int wm   = (wid & 3) * 32;   // 4 warps over M=128
    const int wn   = (wid >> 2) * 64;  // 2 warps over N=128
    const int g    = lane >> 2;        // groupID 0..7
    const int t    = lane & 3;         // threadID_in_group 0..3

    const int total = g_tp[NE] * NT;

    for (int work = blockIdx.x; work < total; work += gridDim.x) {
        const int mt = work / NT;
        const int nt = work - mt * NT;
        int e = 0;
        while (g_tp[e + 1] <= mt) e++;
        const int m0   = g_off[e] + (mt - g_tp[e]) * 128;
        const int mEnd = g_off[e + 1];
        const int n0   = nt * 128;
        const float* Be = Bw + (size_t)e * K * N + n0;   // W[e][k][n0..]

        // -------- loader: k-tile kt (32 k) -> stage s --------
        auto load_tile = [&](int kt, int s) {
            const uint32_t ab = sb + (uint32_t)s * STAGE_BYTES;
            const uint32_t bb = ab + A_WORDS * 4;
            // A: 128 rows x 32 fp32 = 8 chunks of 16B per row
#pragma unroll
            for (int j = 0; j < 4; j++) {
                int idx = tid + j * 256;              // 0..1023
                int row = idx >> 3, c = idx & 7;
                int rg = min(m0 + row, mEnd - 1);
                const float* src;
                if (FIRST)
                    src = X + (size_t)g_slot_token[rg] * K + kt * 32 + c * 4;
                else
                    src = g_h + (size_t)rg * K + kt * 32 + c * 4;
                CP_ASYNC16(ab + (uint32_t)(row * 144 + c * 16), src);
            }
            // B: 32 k-rows x 128 fp32 = 32 chunks of 16B per row
#pragma unroll
            for (int j = 0; j < 4; j++) {
                int idx = tid + j * 256;              // 0..1023
                int row = idx >> 5, c = idx & 31;
                const float* src = Be + (size_t)(kt * 32 + row) * N + c * 4;
                CP_ASYNC16(bb + (uint32_t)(row * 544 + c * 16), src);
            }
        };

        float acc[2][8][4];
#pragma unroll
        for (int mi = 0; mi < 2; mi++)
#pragma unroll
            for (int ni = 0; ni < 8; ni++)
#pragma unroll
                for (int q = 0; q < 4; q++) acc[mi][ni][q] = 0.f;

        load_tile(0, 0); CP_COMMIT();
        load_tile(1, 1); CP_COMMIT();

        for (int i = 0; i < KT; i++) {
            CP_WAIT1();
            __syncthreads();
            const uint32_t* Aw = dsw + (i & 1) * STAGE_WORDS;  // [m][36]
            const uint32_t* Bs = Aw + A_WORDS;                 // [k][136]
#pragma unroll
            for (int ks = 0; ks < 4; ks++) {      // 4 x k8 within BK=32
                const int kk = ks * 8;
                uint32_t af[2][4];
#pragma unroll
                for (int mi = 0; mi < 2; mi++) {
                    const int r = wm + mi * 16 + g;
                    af[mi][0] = Aw[r * 36 + kk + t];            // (row,   k=t)
                    af[mi][1] = Aw[(r + 8) * 36 + kk + t];      // (row+8, k=t)
                    af[mi][2] = Aw[r * 36 + kk + t + 4];        // (row,   k=t+4)
                    af[mi][3] = Aw[(r + 8) * 36 + kk + t + 4];  // (row+8, k=t+4)
                }
#pragma unroll
                for (int ni = 0; ni < 8; ni++) {
                    const int c = wn + ni * 8 + g;
                    uint32_t b0 = Bs[(kk + t) * 136 + c];       // (k=t,   n)
                    uint32_t b1 = Bs[(kk + t + 4) * 136 + c];   // (k=t+4, n)
                    MMA_TF32(acc[0][ni], af[0][0], af[0][1], af[0][2], af[0][3], b0, b1);
                    MMA_TF32(acc[1][ni], af[1][0], af[1][1], af[1][2], af[1][3], b0, b1);
                }
            }
            __syncthreads();
            if (i + 2 < KT) load_tile(i + 2, i & 1);
            CP_COMMIT();
        }

        // -------- epilogue (mapping verified in round 2) --------
        float* Out = FIRST ? g_h : g_o;
#pragma unroll
        for (int mi = 0; mi < 2; mi++) {
            const int row0 = m0 + wm + mi * 16 + g;
            const int row1 = row0 + 8;
#pragma unroll
            for (int ni = 0; ni < 8; ni++) {
                const int col = n0 + wn + ni * 8 + 2 * t;
                const float2 bb = *(const float2*)(bias + e * N + col);
                float v0 = acc[mi][ni][0] + bb.x;
                float v1 = acc[mi][ni][1] + bb.y;
                float v2 = acc[mi][ni][2] + bb.x;
                float v3 = acc[mi][ni][3] + bb.y;
                if (FIRST) {
                    v0 = gelu(v0); v1 = gelu(v1); v2 = gelu(v2); v3 = gelu(v3);
                }
                if (row0 < mEnd) {
                    float2 o = {v0, v1};
                    *(float2*)(Out + (size_t)row0 * N + col) = o;
                }
                if (row1 < mEnd) {
                    float2 o = {v2, v3};
                    *(float2*)(Out + (size_t)row1 * N + col) = o;
                }
            }
        }
        __syncthreads();   // stages fully consumed before next work's loads
    }
}

// ---------------- combine: y = x + w0*o[s0] + w1*o[s1] ----------------------
__global__ void k_combine(const float* __restrict__ x, float* __restrict__ y,
                          int T) {
    int i = blockIdx.x * blockDim.x + threadIdx.x;
    int total = T * (DIM / 4);
    if (i >= total) return;
    int t = i / (DIM / 4);
    int d = (i - t * (DIM / 4)) * 4;
    float w0 = g_tw[2 * t], w1 = g_tw[2 * t + 1];
    int s0 = g_slot_of[2 * t], s1 = g_slot_of[2 * t + 1];
    float4 xv = *(const float4*)(x + (size_t)t * DIM + d);
    float4 o0 = *(const float4*)(g_o + (size_t)s0 * DIM + d);
    float4 o1 = *(const float4*)(g_o + (size_t)s1 * DIM + d);
    float4 r;
    r.x = xv.x + w0 * o0.x + w1 * o1.x;
    r.y = xv.y + w0 * o0.y + w1 * o1.y;
    r.z = xv.z + w0 * o0.z + w1 * o1.z;
    r.w = xv.w + w0 * o0.w + w1 * o1.w;
    *(float4*)(y + (size_t)t * DIM + d) = r;
}

// ---------------- launch -----------------------------------------------------
extern "C" void kernel_launch(void* const* d_in, const int* in_sizes, int n_in,
                              void* d_out, int out_size) {
    const float* x  = (const float*)d_in[0];
    const float* Wr = (const float*)d_in[1];
    const float* br = (const float*)d_in[2];
    const float* W1 = (const float*)d_in[3];
    const float* b1 = (const float*)d_in[4];
    const float* W2 = (const float*)d_in[5];
    const float* b2 = (const float*)d_in[6];
    float* y = (float*)d_out;
    const int T = in_sizes[0] / DIM;

    cudaFuncSetAttribute(k_gemm<true>,  cudaFuncAttributeMaxDynamicSharedMemorySize, GEMM_SMEM);
    cudaFuncSetAttribute(k_gemm<false>, cudaFuncAttributeMaxDynamicSharedMemorySize, GEMM_SMEM);

    k_init<<<1, 32>>>();
    k_router<<<(T + 7) / 8, 256>>>(x, Wr, br, T);
    k_scan<<<1, 32>>>();
    k_scatter<<<(2 * T + 255) / 256, 256>>>(T);
    k_gemm<true ><<<296, 256, GEMM_SMEM>>>(x, W1, b1);
    k_gemm<false><<<296, 256, GEMM_SMEM>>>(nullptr, W2, b2);
    k_combine<<<(T * (DIM / 4) + 255) / 256, 256>>>(x, y, T);
}